// round 12
// baseline (speedup 1.0000x reference)
#include <cuda_runtime.h>

// SoftDepthShader: softmax depth blend over K=50 slots per pixel.
//
// R9 architecture change: transpose-through-smem, THREAD-per-pixel.
//  - Block = 64 threads = 64 pixels. Stage zbuf + pix_to_face for the block's
//    64 rows (200 B each) into smem: coalesced LDG.128 from global, XOR-swizzled
//    STS.64 (rows padded to 256 B, slot j at byte ((j^(r&7))<<4)) so per-thread
//    row reads are bank-conflict-free LDS.128.
//  - Each thread then processes its own pixel serially: no shuffles, no
//    ballots, no cross-lane routing => ~14 issue slots/pixel vs ~96 in the
//    warp-cooperative design (which was issue-bound at 81%).
//  - dists is NOT bulk-loaded: survivors of the softmax (exp2 underflow cutoff,
//    ~1.4/pixel) are found from a bitmask pass, and only their dists elements
//    are fetched from global (~25 MB instead of 105 MB). Total DRAM ~237 MB.
//  - 32 KB smem/block -> 6 blocks/SM; phase-offset blocks overlap staging
//    (DRAM) with compute (smem/ALU).

#define KSLOTS 50
#define ZFAR 100.0f
#define EPSV 1e-10f
#define L2E 1.4426950408889634f
#define NAC (-(L2E * 1.0e4f / 99.0f))     // a = (ZFAR-z)*AC = fma(z, NAC, ZAC)
#define ZAC (ZFAR * L2E * 1.0e4f / 99.0f)
#define SIG_L2E (L2E * 1.0e4f)
#define EPS_A (EPSV * L2E * 1.0e4f)
#define NEG_BIG (-1e30f)

#define PXB 64                              // pixels (= threads) per block
#define F4_PER_BLK (PXB * KSLOTS / 4)       // 800 float4 per array per block
#define ROW_BYTES 256                       // 16 swizzle slots of 16 B (13 used)
#define P_OFF (PXB * ROW_BYTES)             // 16 KB
#define SMEM_BYTES (2 * PXB * ROW_BYTES)    // 32 KB

__device__ __forceinline__ float fast_exp2(float x) {
    float y;
    asm("ex2.approx.ftz.f32 %0, %1;" : "=f"(y) : "f"(x));
    return y;
}

__global__ __launch_bounds__(PXB) void soft_depth_kernel(
    const float4* __restrict__ zbuf4,
    const int4*   __restrict__ p2f4,
    const float*  __restrict__ dists,
    float* __restrict__ out)
{
    extern __shared__ char sm[];
    char* smz = sm;
    char* smp = sm + P_OFF;
    const int tid = threadIdx.x;

    // ---- stage z and p: coalesced LDG.128, swizzled STS.64 pairs ----
    // (8-byte element pairs never straddle a 50-float row: 50 is even)
    const int gbase = blockIdx.x * F4_PER_BLK;
    for (int i = tid; i < F4_PER_BLK; i += PXB) {
        float4 zv = __ldg(zbuf4 + gbase + i);
        int4   pv = __ldg(p2f4  + gbase + i);
        const int e  = 4 * i;
        const int r0 = e / KSLOTS,       c0 = e - KSLOTS * r0;
        const int r1 = (e + 2) / KSLOTS, c1 = (e + 2) - KSLOTS * r1;
        const int o0 = r0 * ROW_BYTES + (((c0 >> 2) ^ (r0 & 7)) << 4) + ((c0 & 3) << 2);
        const int o1 = r1 * ROW_BYTES + (((c1 >> 2) ^ (r1 & 7)) << 4) + ((c1 & 3) << 2);
        *(float2*)(smz + o0) = make_float2(zv.x, zv.y);
        *(float2*)(smz + o1) = make_float2(zv.z, zv.w);
        *(int2*)  (smp + o0) = make_int2(pv.x, pv.y);
        *(int2*)  (smp + o1) = make_int2(pv.z, pv.w);
    }
    __syncthreads();

    // ---- thread-per-pixel compute ----
    const int r = tid;
    const int sw = (r & 7) << 4;                 // row swizzle (bits 4-6)
    const char* zrow = smz + r * ROW_BYTES;
    const char* prow = smp + r * ROW_BYTES;

    // pass 1: per-pixel max of a (masked -> -1e30, beaten by EPS_A clamp)
    float acc0 = NEG_BIG, acc1 = NEG_BIG, acc2 = NEG_BIG, acc3 = NEG_BIG;
    #pragma unroll
    for (int j = 0; j < 12; j++) {
        const float4 z4 = *(const float4*)(zrow + ((j << 4) ^ sw));
        const int4   p4 = *(const int4*)  (prow + ((j << 4) ^ sw));
        acc0 = fmaxf(acc0, p4.x >= 0 ? fmaf(z4.x, NAC, ZAC) : NEG_BIG);
        acc1 = fmaxf(acc1, p4.y >= 0 ? fmaf(z4.y, NAC, ZAC) : NEG_BIG);
        acc2 = fmaxf(acc2, p4.z >= 0 ? fmaf(z4.z, NAC, ZAC) : NEG_BIG);
        acc3 = fmaxf(acc3, p4.w >= 0 ? fmaf(z4.w, NAC, ZAC) : NEG_BIG);
    }
    {   // elements 48,49 live in the low half of slot 12
        const float2 z2 = *(const float2*)(zrow + ((12 << 4) ^ sw));
        const int2   p2 = *(const int2*)  (prow + ((12 << 4) ^ sw));
        acc0 = fmaxf(acc0, p2.x >= 0 ? fmaf(z2.x, NAC, ZAC) : NEG_BIG);
        acc1 = fmaxf(acc1, p2.y >= 0 ? fmaf(z2.y, NAC, ZAC) : NEG_BIG);
    }
    const float amax = fmaxf(fmaxf(fmaxf(acc0, acc1), fmaxf(acc2, acc3)), EPS_A);
    const float cut  = amax - 126.0f;            // exp2 flush-to-zero cutoff

    // pass 2: survivor bitmask (re-stream z,p from smem; same FMA -> same bits)
    unsigned m0 = 0, m1 = 0;
    #pragma unroll
    for (int j = 0; j < 12; j++) {
        const float4 z4 = *(const float4*)(zrow + ((j << 4) ^ sw));
        const int4   p4 = *(const int4*)  (prow + ((j << 4) ^ sw));
        unsigned b = 0;
        b |= (p4.x >= 0 && fmaf(z4.x, NAC, ZAC) > cut) ? 1u : 0u;
        b |= (p4.y >= 0 && fmaf(z4.y, NAC, ZAC) > cut) ? 2u : 0u;
        b |= (p4.z >= 0 && fmaf(z4.z, NAC, ZAC) > cut) ? 4u : 0u;
        b |= (p4.w >= 0 && fmaf(z4.w, NAC, ZAC) > cut) ? 8u : 0u;
        if (j < 8) m0 |= b << (4 * j);
        else       m1 |= b << (4 * j - 32);
    }
    {
        const float2 z2 = *(const float2*)(zrow + ((12 << 4) ^ sw));
        const int2   p2 = *(const int2*)  (prow + ((12 << 4) ^ sw));
        m1 |= (p2.x >= 0 && fmaf(z2.x, NAC, ZAC) > cut) ? (1u << 16) : 0u;
        m1 |= (p2.y >= 0 && fmaf(z2.y, NAC, ZAC) > cut) ? (1u << 17) : 0u;
    }

    // gather survivors (~1.4/pixel): scattered global dists loads only here
    float w = 0.f, wz = 0.f;
    const int pixbase = (blockIdx.x * PXB + r) * KSLOTS;
    while (m0) {
        const int k = __ffs(m0) - 1;  m0 &= m0 - 1;
        const float zk = *(const float*)(zrow + ((((k >> 2) << 4) ^ sw) + ((k & 3) << 2)));
        const float dk = __ldg(dists + pixbase + k);
        const float ak = fmaf(zk, NAC, ZAC);
        const float wk = __fdividef(fast_exp2(ak - amax),
                                    1.0f + fast_exp2(dk * SIG_L2E));
        w += wk;  wz = fmaf(wk, zk, wz);
    }
    while (m1) {
        const int k = __ffs(m1) - 1 + 32;  m1 &= m1 - 1;
        const float zk = *(const float*)(zrow + ((((k >> 2) << 4) ^ sw) + ((k & 3) << 2)));
        const float dk = __ldg(dists + pixbase + k);
        const float ak = fmaf(zk, NAC, ZAC);
        const float wk = __fdividef(fast_exp2(ak - amax),
                                    1.0f + fast_exp2(dk * SIG_L2E));
        w += wk;  wz = fmaf(wk, zk, wz);
    }

    const float delta = fmaxf(fast_exp2(EPS_A - amax), EPSV);
    out[blockIdx.x * PXB + r] = (wz + delta) * __fdividef(1.0f, w + delta);  // BG=1
}

extern "C" void kernel_launch(void* const* d_in, const int* in_sizes, int n_in,
                              void* d_out, int out_size)
{
    const float4* zbuf4 = (const float4*)d_in[0];
    const float*  dists = (const float*)d_in[1];
    const int4*   p2f4  = (const int4*)d_in[2];
    float*        out   = (float*)d_out;

    cudaFuncSetAttribute(soft_depth_kernel,
                         cudaFuncAttributeMaxDynamicSharedMemorySize, SMEM_BYTES);

    const int npix   = in_sizes[0] / KSLOTS;  // 524288
    const int blocks = npix / PXB;            // 8192

    soft_depth_kernel<<<blocks, PXB, SMEM_BYTES>>>(zbuf4, p2f4, dists, out);
}

// round 13
// speedup vs baseline: 1.6584x; 1.6584x over previous
#include <cuda_runtime.h>

// SoftDepthShader: softmax depth blend over K=50 slots per pixel.
//
// R10 = R9 architecture (thread-per-pixel through smem) with fixed geometry:
//  - Stage ONE array: a = mask ? (ZFAR - z)*AC : -1e30, computed during the
//    coalesced staging pass (LDG.128 z + LDG.128 p2f -> STS.128 a). z is
//    recovered later as z = ZFAR - a/AC (affine, ~1e-7 rel err).
//  - Unpadded 200 B rows: smem image is LINEAR in element index (row*50+k = e),
//    so stores need no swizzle math; row reads are LDS.64 with 2-way conflicts.
//  - 256 pixels/block, 256 threads, 50 KB smem -> 4 blocks/SM = 32 warps/SM
//    (R9 died at 12 warps/SM).
//  - dists loaded sparsely for survivors only (~1.4/pixel, ~23 MB vs 105 MB);
//    survivor bitmask first, then a short gather loop (few exposed latencies).
// Sparsity: exp2(a - amax) flushes to 0 unless a within 126 of amax; dropped
// terms <= 2^-126 vs denom >= 1e-10.

#define KSLOTS 50
#define ZFAR 100.0f
#define EPSV 1e-10f
#define L2E 1.4426950408889634f
#define NAC (-(L2E * 1.0e4f / 99.0f))       // a = (ZFAR-z)*AC = fma(z, NAC, ZAC)
#define ZAC (ZFAR * L2E * 1.0e4f / 99.0f)
#define NINV_AC (-(99.0f / (1.0e4f * L2E))) // z = fma(a, NINV_AC, ZFAR)
#define SIG_L2E (L2E * 1.0e4f)
#define EPS_A (EPSV * L2E * 1.0e4f)
#define NEG_BIG (-1e30f)

#define PXB 256                              // pixels (= threads) per block
#define F4_PER_BLK (PXB * KSLOTS / 4)        // 3200 float4 per array per block
#define SMEM_BYTES (PXB * KSLOTS * 4)        // 51200 B

__device__ __forceinline__ float fast_exp2(float x) {
    float y;
    asm("ex2.approx.ftz.f32 %0, %1;" : "=f"(y) : "f"(x));
    return y;
}

__global__ __launch_bounds__(PXB) void soft_depth_kernel(
    const float4* __restrict__ zbuf4,
    const int4*   __restrict__ p2f4,
    const float*  __restrict__ dists,
    float* __restrict__ out)
{
    extern __shared__ float a_s[];           // [PXB * KSLOTS], linear in element
    const int tid = threadIdx.x;

    // ---- staging: coalesced LDG.128 (z, p2f) -> a-values, STS.128 ----
    const int gbase = blockIdx.x * F4_PER_BLK;
    #pragma unroll 4
    for (int i = tid; i < F4_PER_BLK; i += PXB) {
        const float4 zv = __ldg(zbuf4 + gbase + i);
        const int4   pv = __ldg(p2f4  + gbase + i);
        float4 av;
        av.x = (pv.x >= 0) ? fmaf(zv.x, NAC, ZAC) : NEG_BIG;
        av.y = (pv.y >= 0) ? fmaf(zv.y, NAC, ZAC) : NEG_BIG;
        av.z = (pv.z >= 0) ? fmaf(zv.z, NAC, ZAC) : NEG_BIG;
        av.w = (pv.w >= 0) ? fmaf(zv.w, NAC, ZAC) : NEG_BIG;
        ((float4*)a_s)[i] = av;              // linear: element e lives at a_s[e]
    }
    __syncthreads();

    // ---- thread-per-pixel compute: no shuffles, no ballots ----
    const float2* row2 = (const float2*)(a_s + tid * KSLOTS);  // 8B-aligned
    const float*  rowf = a_s + tid * KSLOTS;

    // pass 1: per-pixel max of a
    float m0 = NEG_BIG, m1 = NEG_BIG;
    #pragma unroll
    for (int j = 0; j < 25; j++) {
        const float2 v = row2[j];
        m0 = fmaxf(m0, v.x);
        m1 = fmaxf(m1, v.y);
    }
    const float amax = fmaxf(fmaxf(m0, m1), EPS_A);
    const float cut  = amax - 126.0f;        // exp2 flush-to-zero cutoff

    // pass 2: survivor bitmask (values reread from smem: bitwise identical)
    unsigned long long mask = 0ull;
    #pragma unroll
    for (int j = 0; j < 25; j++) {
        const float2 v = row2[j];
        if (v.x > cut) mask |= 1ull << (2 * j);
        if (v.y > cut) mask |= 1ull << (2 * j + 1);
    }

    // gather survivors (~1.4/pixel): only here do we touch dists (scattered)
    float w = 0.f, wz = 0.f;
    const int pixbase = (blockIdx.x * PXB + tid) * KSLOTS;
    while (mask) {
        const int k = __ffsll(mask) - 1;  mask &= mask - 1;
        const float dk = __ldg(dists + pixbase + k);
        const float ak = rowf[k];
        const float zk = fmaf(ak, NINV_AC, ZFAR);   // recover z
        const float wk = __fdividef(fast_exp2(ak - amax),
                                    1.0f + fast_exp2(dk * SIG_L2E));
        w += wk;  wz = fmaf(wk, zk, wz);
    }

    const float delta = fmaxf(fast_exp2(EPS_A - amax), EPSV);
    // BG_BLUE = 1.0 -> numerator + delta
    out[blockIdx.x * PXB + tid] = (wz + delta) * __fdividef(1.0f, w + delta);
}

extern "C" void kernel_launch(void* const* d_in, const int* in_sizes, int n_in,
                              void* d_out, int out_size)
{
    const float4* zbuf4 = (const float4*)d_in[0];
    const float*  dists = (const float*)d_in[1];
    const int4*   p2f4  = (const int4*)d_in[2];
    float*        out   = (float*)d_out;

    cudaFuncSetAttribute(soft_depth_kernel,
                         cudaFuncAttributeMaxDynamicSharedMemorySize, SMEM_BYTES);

    const int npix   = in_sizes[0] / KSLOTS;  // 524288
    const int blocks = npix / PXB;            // 2048

    soft_depth_kernel<<<blocks, PXB, SMEM_BYTES>>>(zbuf4, p2f4, dists, out);
}

// round 15
// speedup vs baseline: 1.6739x; 1.0093x over previous
#include <cuda_runtime.h>

// SoftDepthShader: softmax depth blend over K=50 slots per pixel.
//
// R11 = R10 minus the block barrier: WARP-AUTONOMOUS tiles.
//  - Tile = 1 warp = 32 pixels = 6.4 KB smem slice. The warp stages its own
//    32 rows (coalesced LDG.128 of z + p2f, fused into a-values, STS.128),
//    then __syncwarp() (~23 cyc) and computes thread-per-pixel. No
//    __syncthreads anywhere -> 32 warps/SM at independent stage/compute
//    phases keep DRAM continuously fed (R10's block-wide barrier made all
//    4 resident blocks stage/compute in lockstep; DRAM idled at 60%).
//  - a = mask ? (ZFAR - z)*AC : -1e30 stored in smem (one array, not two);
//    z recovered as z = fma(a, NINV_AC, ZFAR) (~1e-7 rel err).
//  - dists loaded sparsely for survivors only (exp2-underflow cutoff,
//    ~1.4/pixel, ~23 MB vs 105 MB bulk). Total DRAM ~237 MB.
// Dropped terms <= 2^-126 vs denom >= 1e-10 -> immaterial at 1e-3 tolerance.

#define KSLOTS 50
#define ZFAR 100.0f
#define EPSV 1e-10f
#define L2E 1.4426950408889634f
#define NAC (-(L2E * 1.0e4f / 99.0f))       // a = (ZFAR-z)*AC = fma(z, NAC, ZAC)
#define ZAC (ZFAR * L2E * 1.0e4f / 99.0f)
#define NINV_AC (-(99.0f / (1.0e4f * L2E))) // z = fma(a, NINV_AC, ZFAR)
#define SIG_L2E (L2E * 1.0e4f)
#define EPS_A (EPSV * L2E * 1.0e4f)
#define NEG_BIG (-1e30f)

#define THREADS 256
#define WARPS (THREADS / 32)
#define PXW 32                               // pixels per warp-tile
#define F4_PER_WARP (PXW * KSLOTS / 4)       // 400 float4 per array per warp
#define SLICE_FLOATS (PXW * KSLOTS)          // 1600 floats = 6.4 KB
#define SMEM_BYTES (WARPS * SLICE_FLOATS * 4)  // 51200 B

__device__ __forceinline__ float fast_exp2(float x) {
    float y;
    asm("ex2.approx.ftz.f32 %0, %1;" : "=f"(y) : "f"(x));
    return y;
}

__global__ __launch_bounds__(THREADS) void soft_depth_kernel(
    const float4* __restrict__ zbuf4,
    const int4*   __restrict__ p2f4,
    const float*  __restrict__ dists,
    float* __restrict__ out)
{
    extern __shared__ float a_s[];
    const int tid  = threadIdx.x;
    const int wid  = tid >> 5;
    const int lane = tid & 31;

    float* slice = a_s + wid * SLICE_FLOATS;           // this warp's 32 rows
    const int warp_global = blockIdx.x * WARPS + wid;  // tile index
    const int gbase = warp_global * F4_PER_WARP;       // float4 base in arrays

    // ---- stage: coalesced LDG.128 (z, p2f) -> a-values, STS.128 ----
    // 400 float4 over 32 lanes: 12.5 avg iterations, guarded loop
    #pragma unroll 4
    for (int i = lane; i < F4_PER_WARP; i += 32) {
        const float4 zv = __ldg(zbuf4 + gbase + i);
        const int4   pv = __ldg(p2f4  + gbase + i);
        float4 av;
        av.x = (pv.x >= 0) ? fmaf(zv.x, NAC, ZAC) : NEG_BIG;
        av.y = (pv.y >= 0) ? fmaf(zv.y, NAC, ZAC) : NEG_BIG;
        av.z = (pv.z >= 0) ? fmaf(zv.z, NAC, ZAC) : NEG_BIG;
        av.w = (pv.w >= 0) ? fmaf(zv.w, NAC, ZAC) : NEG_BIG;
        ((float4*)slice)[i] = av;                      // linear in element idx
    }
    __syncwarp();

    // ---- thread-per-pixel compute: no shuffles, no ballots, no bar.sync ----
    const float2* row2 = (const float2*)(slice + lane * KSLOTS);  // 8B-aligned
    const float*  rowf = slice + lane * KSLOTS;

    // pass 1: per-pixel max of a
    float m0 = NEG_BIG, m1 = NEG_BIG;
    #pragma unroll
    for (int j = 0; j < 25; j++) {
        const float2 v = row2[j];
        m0 = fmaxf(m0, v.x);
        m1 = fmaxf(m1, v.y);
    }
    const float amax = fmaxf(fmaxf(m0, m1), EPS_A);
    const float cut  = amax - 126.0f;        // exp2 flush-to-zero cutoff

    // pass 2: survivor bitmask (reread smem: bitwise identical values)
    unsigned long long mask = 0ull;
    #pragma unroll
    for (int j = 0; j < 25; j++) {
        const float2 v = row2[j];
        if (v.x > cut) mask |= 1ull << (2 * j);
        if (v.y > cut) mask |= 1ull << (2 * j + 1);
    }

    // sparse gather (~1.4 survivors/pixel): only dists touch, scattered
    float w = 0.f, wz = 0.f;
    const int pixbase = (warp_global * PXW + lane) * KSLOTS;
    while (mask) {
        const int k = __ffsll(mask) - 1;  mask &= mask - 1;
        const float dk = __ldg(dists + pixbase + k);
        const float ak = rowf[k];
        const float zk = fmaf(ak, NINV_AC, ZFAR);      // recover z
        const float wk = __fdividef(fast_exp2(ak - amax),
                                    1.0f + fast_exp2(dk * SIG_L2E));
        w += wk;  wz = fmaf(wk, zk, wz);
    }

    const float delta = fmaxf(fast_exp2(EPS_A - amax), EPSV);
    // BG_BLUE = 1.0 -> numerator + delta
    out[warp_global * PXW + lane] =
        (wz + delta) * __fdividef(1.0f, w + delta);
}

extern "C" void kernel_launch(void* const* d_in, const int* in_sizes, int n_in,
                              void* d_out, int out_size)
{
    const float4* zbuf4 = (const float4*)d_in[0];
    const float*  dists = (const float*)d_in[1];
    const int4*   p2f4  = (const int4*)d_in[2];
    float*        out   = (float*)d_out;

    cudaFuncSetAttribute(soft_depth_kernel,
                         cudaFuncAttributeMaxDynamicSharedMemorySize, SMEM_BYTES);

    const int npix   = in_sizes[0] / KSLOTS;      // 524288
    const int blocks = npix / (WARPS * PXW);      // 2048

    soft_depth_kernel<<<blocks, THREADS, SMEM_BYTES>>>(zbuf4, p2f4, dists, out);
}

// round 17
// speedup vs baseline: 1.7822x; 1.0647x over previous
#include <cuda_runtime.h>

// SoftDepthShader: softmax depth blend over K=50 slots per pixel.
//
// R12: 8-LANE pixel-pair groups, no smem, all-bulk loads.
//  - Pair = 2 pixels = 100 floats = 25 float4 (16B-aligned for every pair).
//  - Warp = 4 groups x 8 lanes; group g owns pair 4*warp+g. Lane s in group
//    loads float4 s, s+8, s+16 (+24 on s==0) of each array -> ~10 LDG.128
//    per warp, 4800 B in flight, ZERO dependent loads.
//  - Reductions: 3-level shfl bfly (xor 1,2,4) stays inside 8-lane groups and
//    serves all 4 groups in the same instructions -> ~19 issue slots/pixel
//    (R8's 32-lane design paid ~90; R10/11 proved ~15 is enough to compute).
//  - z,p regs die early: a = mask ? (ZFAR-z)*AC : -1e30; z recovered as
//    z = fma(a, NINV_AC, ZFAR) (~1e-7 rel err).
//  - Survivor gating: exp2(a-amax) flushes to 0 unless a > amax-126
//    (~1.4 survivors/pixel); dropped terms <= 2^-126 vs denom >= 1e-10.

#define KSLOTS 50
#define ZFAR 100.0f
#define EPSV 1e-10f
#define L2E 1.4426950408889634f
#define NAC (-(L2E * 1.0e4f / 99.0f))       // a = (ZFAR-z)*AC = fma(z, NAC, ZAC)
#define ZAC (ZFAR * L2E * 1.0e4f / 99.0f)
#define NINV_AC (-(99.0f / (1.0e4f * L2E))) // z = fma(a, NINV_AC, ZFAR)
#define SIG_L2E (L2E * 1.0e4f)
#define EPS_A (EPSV * L2E * 1.0e4f)
#define NEG_BIG (-1e30f)

__device__ __forceinline__ float fast_exp2(float x) {
    float y;
    asm("ex2.approx.ftz.f32 %0, %1;" : "=f"(y) : "f"(x));
    return y;
}

__device__ __forceinline__ void a_of(const float4& z, const int4& p, float* a) {
    a[0] = (p.x >= 0) ? fmaf(z.x, NAC, ZAC) : NEG_BIG;
    a[1] = (p.y >= 0) ? fmaf(z.y, NAC, ZAC) : NEG_BIG;
    a[2] = (p.z >= 0) ? fmaf(z.z, NAC, ZAC) : NEG_BIG;
    a[3] = (p.w >= 0) ? fmaf(z.w, NAC, ZAC) : NEG_BIG;
}

__device__ __forceinline__ void acc(float a, float d, float amax, float cut,
                                    float& w, float& wz) {
    if (a > cut) {
        const float wk = __fdividef(fast_exp2(a - amax),
                                    1.0f + fast_exp2(d * SIG_L2E));
        w += wk;
        wz = fmaf(wk, fmaf(a, NINV_AC, ZFAR), wz);   // z recovered from a
    }
}

__global__ __launch_bounds__(256) void soft_depth_kernel(
    const float4* __restrict__ zbuf4,
    const float4* __restrict__ dists4,
    const int4*   __restrict__ p2f4,
    float2* __restrict__ out2)
{
    const unsigned FULL = 0xFFFFFFFFu;
    const int wp   = (blockIdx.x * blockDim.x + threadIdx.x) >> 5;  // warp id
    const int lane = threadIdx.x & 31;
    const int g    = lane >> 3;            // group 0..3 -> pair 4*wp+g
    const int s    = lane & 7;             // sublane within group

    const int pairIdx = 4 * wp + g;
    const int fb = pairIdx * 25;           // float4 base of this pair

    // ---- all bulk loads issued up front (max MLP, no dependent chains) ----
    const float4 zq0 = __ldg(zbuf4 + fb + s);
    const float4 zq1 = __ldg(zbuf4 + fb + s + 8);
    const float4 zq2 = __ldg(zbuf4 + fb + s + 16);
    const float4 dq0 = __ldg(dists4 + fb + s);
    const float4 dq1 = __ldg(dists4 + fb + s + 8);
    const float4 dq2 = __ldg(dists4 + fb + s + 16);
    const int4   pq0 = __ldg(p2f4 + fb + s);
    const int4   pq1 = __ldg(p2f4 + fb + s + 8);
    const int4   pq2 = __ldg(p2f4 + fb + s + 16);
    float4 zq3 = make_float4(0.f, 0.f, 0.f, 0.f);
    float4 dq3 = zq3;
    int4   pq3 = make_int4(-1, -1, -1, -1);
    if (s == 0) {                          // 25th float4 (elems 96-99, pixel1)
        zq3 = __ldg(zbuf4 + fb + 24);
        dq3 = __ldg(dists4 + fb + 24);
        pq3 = __ldg(p2f4 + fb + 24);
    }

    // ---- a-values (z,p regs die here) ----
    float a0[4], a1[4], a2[4], a3[4];
    a_of(zq0, pq0, a0);                    // elems 4s..4s+3       -> pixel0
    a_of(zq1, pq1, a1);                    // elems 32+4s..35+4s   -> split
    a_of(zq2, pq2, a2);                    // elems 64+4s..67+4s   -> pixel1
    a_of(zq3, pq3, a3);                    // elems 96..99         -> pixel1

    // q1 routing: comps {x,y} -> pixel0 iff s<=4; comps {z,w} -> iff s<=3
    const bool r01 = (s <= 4);
    const bool r23 = (s <= 3);

    // ---- per-lane partial maxes ----
    const float m1xy = fmaxf(a1[0], a1[1]);
    const float m1zw = fmaxf(a1[2], a1[3]);
    float pm0 = fmaxf(fmaxf(a0[0], a0[1]), fmaxf(a0[2], a0[3]));
    float pm1 = fmaxf(fmaxf(a2[0], a2[1]), fmaxf(a2[2], a2[3]));
    pm1 = fmaxf(pm1, fmaxf(fmaxf(a3[0], a3[1]), fmaxf(a3[2], a3[3])));
    pm0 = fmaxf(pm0, r01 ? m1xy : NEG_BIG);
    pm1 = fmaxf(pm1, r01 ? NEG_BIG : m1xy);
    pm0 = fmaxf(pm0, r23 ? m1zw : NEG_BIG);
    pm1 = fmaxf(pm1, r23 ? NEG_BIG : m1zw);

    // ---- 3-level group bfly (xor 1,2,4 stays within 8-lane groups) ----
    float gm0 = pm0, gm1 = pm1;
    #pragma unroll
    for (int off = 1; off <= 4; off <<= 1) {
        gm0 = fmaxf(gm0, __shfl_xor_sync(FULL, gm0, off));
        gm1 = fmaxf(gm1, __shfl_xor_sync(FULL, gm1, off));
    }
    const float amax0 = fmaxf(gm0, EPS_A);
    const float amax1 = fmaxf(gm1, EPS_A);
    const float cut0  = amax0 - 126.0f;
    const float cut1  = amax1 - 126.0f;

    // ---- survivor-gated weights (lane gate skips ~91% of lanes) ----
    float w0 = 0.f, wz0 = 0.f, w1 = 0.f, wz1 = 0.f;
    if (pm0 > cut0 || pm1 > cut1) {
        acc(a0[0], dq0.x, amax0, cut0, w0, wz0);
        acc(a0[1], dq0.y, amax0, cut0, w0, wz0);
        acc(a0[2], dq0.z, amax0, cut0, w0, wz0);
        acc(a0[3], dq0.w, amax0, cut0, w0, wz0);
        const float am01 = r01 ? amax0 : amax1;
        const float ct01 = r01 ? cut0  : cut1;
        const float am23 = r23 ? amax0 : amax1;
        const float ct23 = r23 ? cut0  : cut1;
        float wa = 0.f, wza = 0.f, wb = 0.f, wzb = 0.f;
        acc(a1[0], dq1.x, am01, ct01, wa, wza);
        acc(a1[1], dq1.y, am01, ct01, wa, wza);
        acc(a1[2], dq1.z, am23, ct23, wb, wzb);
        acc(a1[3], dq1.w, am23, ct23, wb, wzb);
        w0  += (r01 ? wa  : 0.f) + (r23 ? wb  : 0.f);
        wz0 += (r01 ? wza : 0.f) + (r23 ? wzb : 0.f);
        w1  += (r01 ? 0.f : wa)  + (r23 ? 0.f : wb);
        wz1 += (r01 ? 0.f : wza) + (r23 ? 0.f : wzb);
        acc(a2[0], dq2.x, amax1, cut1, w1, wz1);
        acc(a2[1], dq2.y, amax1, cut1, w1, wz1);
        acc(a2[2], dq2.z, amax1, cut1, w1, wz1);
        acc(a2[3], dq2.w, amax1, cut1, w1, wz1);
        acc(a3[0], dq3.x, amax1, cut1, w1, wz1);
        acc(a3[1], dq3.y, amax1, cut1, w1, wz1);
        acc(a3[2], dq3.z, amax1, cut1, w1, wz1);
        acc(a3[3], dq3.w, amax1, cut1, w1, wz1);
    }

    // ---- group sum bfly ----
    #pragma unroll
    for (int off = 1; off <= 4; off <<= 1) {
        w0  += __shfl_xor_sync(FULL, w0,  off);
        wz0 += __shfl_xor_sync(FULL, wz0, off);
        w1  += __shfl_xor_sync(FULL, w1,  off);
        wz1 += __shfl_xor_sync(FULL, wz1, off);
    }

    if (s == 0) {
        const float delta0 = fmaxf(fast_exp2(EPS_A - amax0), EPSV);
        const float delta1 = fmaxf(fast_exp2(EPS_A - amax1), EPSV);
        float2 o;                                   // BG_BLUE = 1
        o.x = (wz0 + delta0) * __fdividef(1.0f, w0 + delta0);
        o.y = (wz1 + delta1) * __fdividef(1.0f, w1 + delta1);
        out2[pairIdx] = o;                          // coalesced STG.64
    }
}

extern "C" void kernel_launch(void* const* d_in, const int* in_sizes, int n_in,
                              void* d_out, int out_size)
{
    const float4* zbuf4  = (const float4*)d_in[0];
    const float4* dists4 = (const float4*)d_in[1];
    const int4*   p2f4   = (const int4*)d_in[2];
    float2*       out2   = (float2*)d_out;

    const int npix  = in_sizes[0] / KSLOTS;    // 524288
    const int warps = npix / 8;                // 65536 (8 pixels per warp)
    const int threads = 256;
    const int blocks = warps / (threads / 32); // 8192

    soft_depth_kernel<<<blocks, threads>>>(zbuf4, dists4, p2f4, out2);
}